// round 1
// baseline (speedup 1.0000x reference)
#include <cuda_runtime.h>
#include <cstdint>

// CRF forward scan: B=out_size/64 batches, T=64 states, S steps.
// alpha[b,j] <- feat[b,t,j] + c_j + m_b + log( sum_i exp(alpha[b,i]-m_b) * W[i][j] )
// W[i][j] = exp(trans[i][j] - c_j), c_j = max_i trans[i][j]   (precomputed once)

#define TT 64

__device__ float g_Wt[TT * TT];  // transposed: g_Wt[j*64 + i] = exp(trans[i][j] - c_j)
__device__ float g_c[TT];

typedef unsigned long long u64;

__device__ __forceinline__ u64 pack2(float lo, float hi) {
    u64 r;
    asm("mov.b64 %0, {%1, %2};" : "=l"(r) : "f"(lo), "f"(hi));
    return r;
}
__device__ __forceinline__ void unpack2(u64 v, float& lo, float& hi) {
    asm("mov.b64 {%0, %1}, %2;" : "=f"(lo), "=f"(hi) : "l"(v));
}
__device__ __forceinline__ u64 ffma2(u64 a, u64 b, u64 c) {
    u64 d;
    asm("fma.rn.f32x2 %0, %1, %2, %3;" : "=l"(d) : "l"(a), "l"(b), "l"(c));
    return d;
}
__device__ __forceinline__ u64 fadd2(u64 a, u64 b) {
    u64 d;
    asm("add.rn.f32x2 %0, %1, %2;" : "=l"(d) : "l"(a), "l"(b));
    return d;
}

// ---------------------------------------------------------------------------
// Precompute W (transposed) and per-column max c. One block of 64 threads.
// ---------------------------------------------------------------------------
__global__ void crf_prep_kernel(const float* __restrict__ trans) {
    int j = threadIdx.x;  // column
    float c = -3.402823466e+38f;
    #pragma unroll
    for (int i = 0; i < TT; i++) c = fmaxf(c, trans[i * TT + j]);
    g_c[j] = c;
    #pragma unroll
    for (int i = 0; i < TT; i++) g_Wt[j * TT + i] = __expf(trans[i * TT + j] - c);
}

// ---------------------------------------------------------------------------
// Main scan: one block per batch, 64 threads (thread j = state j).
// ---------------------------------------------------------------------------
__global__ void __launch_bounds__(64, 8) crf_scan_kernel(
    const float* __restrict__ feats,   // [B, S, 64]
    const float* __restrict__ masks,   // [B, S]
    float* __restrict__ out,           // [B, 64]
    int Sdim)
{
    const int b    = blockIdx.x;
    const int j    = threadIdx.x;
    const int warp = j >> 5;
    const int lane = j & 31;

    __shared__ float s_v[TT];      // exp(alpha - m)
    __shared__ float s_wmax[2];    // per-warp maxima

    // Load W column j (contiguous row of g_Wt) into 32 packed f32x2 registers.
    u64 w[32];
    {
        const float4* wp = reinterpret_cast<const float4*>(&g_Wt[j * TT]);
        #pragma unroll
        for (int q = 0; q < 16; q++) {
            float4 f = wp[q];
            w[2 * q]     = pack2(f.x, f.y);
            w[2 * q + 1] = pack2(f.z, f.w);
        }
    }
    const float cj = g_c[j];

    const float* fb = feats + (size_t)b * Sdim * TT;
    const float* mb = masks + (size_t)b * Sdim;

    float alpha = fb[j];  // alpha0 = feats[b, 0, :]

    // Software-pipelined feat/mask loads (1-step prefetch).
    float fcur = fb[TT + j];
    float mcur = mb[1];

    for (int t = 1; t < Sdim; t++) {
        const int tn = (t + 1 < Sdim) ? (t + 1) : t;
        const float fnext = fb[(size_t)tn * TT + j];
        const float mnext = mb[tn];

        // ---- block max of alpha (2 warps) ----
        float m = alpha;
        #pragma unroll
        for (int o = 16; o > 0; o >>= 1)
            m = fmaxf(m, __shfl_xor_sync(0xffffffffu, m, o));
        if (lane == 0) s_wmax[warp] = m;
        __syncthreads();
        m = fmaxf(s_wmax[0], s_wmax[1]);

        // ---- v_i = exp(alpha_i - m) into shared ----
        s_v[j] = __expf(alpha - m);
        __syncthreads();

        // ---- matvec: P_j = sum_i v_i * W[i][j]  (packed f32x2 FFMA) ----
        const float4* vp = reinterpret_cast<const float4*>(s_v);
        u64 acc[4] = {0ull, 0ull, 0ull, 0ull};
        #pragma unroll
        for (int q = 0; q < 16; q++) {
            float4 f = vp[q];                       // broadcast ld.shared.v4
            acc[(2 * q) & 3]     = ffma2(pack2(f.x, f.y), w[2 * q],     acc[(2 * q) & 3]);
            acc[(2 * q + 1) & 3] = ffma2(pack2(f.z, f.w), w[2 * q + 1], acc[(2 * q + 1) & 3]);
        }
        u64 s = fadd2(fadd2(acc[0], acc[1]), fadd2(acc[2], acc[3]));
        float lo, hi;
        unpack2(s, lo, hi);
        const float P = lo + hi;

        const float na = fcur + cj + m + __logf(P);
        alpha = na * mcur + alpha * (1.0f - mcur);

        fcur = fnext;
        mcur = mnext;
    }

    out[(size_t)b * TT + j] = alpha;
}

// ---------------------------------------------------------------------------
extern "C" void kernel_launch(void* const* d_in, const int* in_sizes, int n_in,
                              void* d_out, int out_size) {
    const float* feats = (const float*)d_in[0];
    const float* masks = (const float*)d_in[1];
    const float* trans = (const float*)d_in[2];
    float* out = (float*)d_out;

    const int Bn   = out_size / TT;
    const int Sdim = in_sizes[0] / (Bn * TT);

    crf_prep_kernel<<<1, TT>>>(trans);
    crf_scan_kernel<<<Bn, TT>>>(feats, masks, out, Sdim);
}